// round 8
// baseline (speedup 1.0000x reference)
#include <cuda_runtime.h>
#include <cstdint>

#define SS 160
#define LL 128
#define DD 256
#define KK 16
#define BB 2048

#define THREADS 256
#define B_PER_BLOCK 64
#define ROWS_PER_WARP 8
#define NBLOCKS (LL * (BB / B_PER_BLOCK))   // 4096

__device__ float    g_H[2 * 256 * DD];      // byte tables, bias folded into H0
__device__ float    g_combo[LL * 8 * DD];   // pos + actor + street per (l, a*4+s)
__device__ float    g_R[65536 * DD];        // relu(LN(h)) per 16-bit pattern (64 MB)
__device__ unsigned g_meta[BB * LL];        // pat | a4s<<16 | valid<<31

// ---------- K1: byte tables + combo ----------
__global__ void precompute1(const float* __restrict__ mlp_w,
                            const float* __restrict__ mlp_b,
                            const float* __restrict__ actor_w,
                            const float* __restrict__ street_w,
                            const float* __restrict__ pos_w)
{
    const int d   = threadIdx.x;
    const int bid = blockIdx.x;
    if (bid < 512) {
        const int half = bid >> 8;
        const int q    = bid & 255;
        float acc = (half == 0) ? mlp_b[d] : 0.0f;
#pragma unroll
        for (int k = 0; k < 8; k++)
            if ((q >> k) & 1) acc += mlp_w[(half * 8 + k) * DD + d];
        g_H[bid * DD + d] = acc;
    } else {
        const int cb = bid - 512;              // l*8 + (a*4+s)
        const int c  = cb & 7;
        const int l  = cb >> 3;
        g_combo[cb * DD + d] =
            actor_w[(c >> 2) * DD + d] + street_w[(c & 3) * DD + d] + pos_w[l * DD + d];
    }
}

// ---------- K2: build R[pat][d] = relu(LN(h(pat))[d]) ----------
__global__ __launch_bounds__(256, 4)
void build_relu(const float* __restrict__ ln_g,
                const float* __restrict__ ln_b)
{
    const int lane = threadIdx.x & 31;
    const int p    = blockIdx.x * 8 + (threadIdx.x >> 5);   // pattern
    const int d0   = lane * 8;

    const float* H0 = g_H + ((p & 255)       ) * DD + d0;
    const float* H1 = g_H + ((p >> 8) + 256  ) * DD + d0;
    const float4 a0 = __ldg((const float4*)H0);
    const float4 a1 = __ldg((const float4*)(H0 + 4));
    const float4 b0 = __ldg((const float4*)H1);
    const float4 b1 = __ldg((const float4*)(H1 + 4));

    const float h0 = a0.x + b0.x, h1 = a0.y + b0.y, h2 = a0.z + b0.z, h3 = a0.w + b0.w;
    const float h4 = a1.x + b1.x, h5 = a1.y + b1.y, h6 = a1.z + b1.z, h7 = a1.w + b1.w;

    float s  = ((h0 + h1) + (h2 + h3)) + ((h4 + h5) + (h6 + h7));
    float sq = fmaf(h0, h0, fmaf(h1, h1, fmaf(h2, h2, h3 * h3)))
             + fmaf(h4, h4, fmaf(h5, h5, fmaf(h6, h6, h7 * h7)));
#pragma unroll
    for (int o = 16; o > 0; o >>= 1) {
        s  += __shfl_xor_sync(0xffffffffu, s,  o);
        sq += __shfl_xor_sync(0xffffffffu, sq, o);
    }
    const float mu   = s * (1.0f / DD);
    const float var  = fmaf(-mu, mu, sq * (1.0f / DD));
    const float rs   = rsqrtf(var + 1e-5f);
    const float nmrs = -mu * rs;

    const float4 gA = __ldg((const float4*)(ln_g + d0));
    const float4 gB = __ldg((const float4*)(ln_g + d0 + 4));
    const float4 bA = __ldg((const float4*)(ln_b + d0));
    const float4 bB = __ldg((const float4*)(ln_b + d0 + 4));

    float4 rA, rB;
    rA.x = fmaxf(fmaf(fmaf(h0, rs, nmrs), gA.x, bA.x), 0.0f);
    rA.y = fmaxf(fmaf(fmaf(h1, rs, nmrs), gA.y, bA.y), 0.0f);
    rA.z = fmaxf(fmaf(fmaf(h2, rs, nmrs), gA.z, bA.z), 0.0f);
    rA.w = fmaxf(fmaf(fmaf(h3, rs, nmrs), gA.w, bA.w), 0.0f);
    rB.x = fmaxf(fmaf(fmaf(h4, rs, nmrs), gB.x, bB.x), 0.0f);
    rB.y = fmaxf(fmaf(fmaf(h5, rs, nmrs), gB.y, bB.y), 0.0f);
    rB.z = fmaxf(fmaf(fmaf(h6, rs, nmrs), gB.z, bB.z), 0.0f);
    rB.w = fmaxf(fmaf(fmaf(h7, rs, nmrs), gB.w, bB.w), 0.0f);

    float* dst = g_R + (size_t)p * DD + d0;
    *(float4*)dst       = rA;
    *(float4*)(dst + 4) = rB;
}

// ---------- K3: metadata pre-pass ----------
__global__ void prepass(const int*   __restrict__ token_ids,
                        const int*   __restrict__ actors,
                        const int*   __restrict__ streets,
                        const float* __restrict__ masks)
{
    const int b = blockIdx.x;
    const int l = threadIdx.x;
    const long idc  = (long)b * SS + l;
    const float4* mp = (const float4*)(masks + idc * KK);
    const float4 m0 = __ldg(mp + 0);
    const float4 m1 = __ldg(mp + 1);
    const float4 m2 = __ldg(mp + 2);
    const float4 m3 = __ldg(mp + 3);

    unsigned pat = 0;
    pat |= (m0.x != 0.f) ? 1u       : 0u;
    pat |= (m0.y != 0.f) ? 1u <<  1 : 0u;
    pat |= (m0.z != 0.f) ? 1u <<  2 : 0u;
    pat |= (m0.w != 0.f) ? 1u <<  3 : 0u;
    pat |= (m1.x != 0.f) ? 1u <<  4 : 0u;
    pat |= (m1.y != 0.f) ? 1u <<  5 : 0u;
    pat |= (m1.z != 0.f) ? 1u <<  6 : 0u;
    pat |= (m1.w != 0.f) ? 1u <<  7 : 0u;
    pat |= (m2.x != 0.f) ? 1u <<  8 : 0u;
    pat |= (m2.y != 0.f) ? 1u <<  9 : 0u;
    pat |= (m2.z != 0.f) ? 1u << 10 : 0u;
    pat |= (m2.w != 0.f) ? 1u << 11 : 0u;
    pat |= (m3.x != 0.f) ? 1u << 12 : 0u;
    pat |= (m3.y != 0.f) ? 1u << 13 : 0u;
    pat |= (m3.z != 0.f) ? 1u << 14 : 0u;
    pat |= (m3.w != 0.f) ? 1u << 15 : 0u;

    const int tok = __ldg(token_ids + idc);
    const int a   = __ldg(actors    + idc);
    const int s   = __ldg(streets   + idc);

    unsigned meta = pat | ((unsigned)(a * 4 + s) << 16);
    if (tok >= 0) meta |= 1u << 31;
    g_meta[b * LL + l] = meta;
}

// ---------- helpers: L2-policy loads/stores ----------
struct __align__(32) F8 { float f[8]; };

__device__ __forceinline__ F8 ldg_keep32(const float* p) {
    unsigned long long r0, r1, r2, r3;
    asm volatile("ld.global.nc.L2::evict_last.v4.b64 {%0,%1,%2,%3}, [%4];"
                 : "=l"(r0), "=l"(r1), "=l"(r2), "=l"(r3) : "l"(p));
    F8 v;
    asm("mov.b64 {%0, %1}, %2;" : "=f"(v.f[0]), "=f"(v.f[1]) : "l"(r0));
    asm("mov.b64 {%0, %1}, %2;" : "=f"(v.f[2]), "=f"(v.f[3]) : "l"(r1));
    asm("mov.b64 {%0, %1}, %2;" : "=f"(v.f[4]), "=f"(v.f[5]) : "l"(r2));
    asm("mov.b64 {%0, %1}, %2;" : "=f"(v.f[6]), "=f"(v.f[7]) : "l"(r3));
    return v;
}
__device__ __forceinline__ void stg_cs(float* p, float4 v) {
    asm volatile("st.global.cs.v4.f32 [%0], {%1,%2,%3,%4};"
                 :: "l"(p), "f"(v.x), "f"(v.y), "f"(v.z), "f"(v.w) : "memory");
}

// ---------- main kernel: out = R[pat] + combo, masked ----------
__global__ __launch_bounds__(THREADS, 4)
void action_emb_kernel(float* __restrict__ out)
{
    const int tid  = threadIdx.x;
    const int lane = tid & 31;
    const int warp = tid >> 5;
    const int d0   = lane * 8;

    const int l     = blockIdx.x & (LL - 1);
    const int chunk = blockIdx.x >> 7;
    const int b0    = chunk * B_PER_BLOCK + warp * ROWS_PER_WARP;

    const float* comboL = g_combo + (l * 8) * DD + d0;

    unsigned m32 = 0;
    if (lane < ROWS_PER_WARP) m32 = g_meta[(b0 + lane) * LL + l];

    int oofs = (b0 * LL + l) * DD + d0;
    const int OSTEP = LL * DD;

#pragma unroll
    for (int it = 0; it < ROWS_PER_WARP; it++) {
        const unsigned mc = __shfl_sync(0xffffffffu, m32, it);
        const float* Rp = g_R + (size_t)(mc & 0xFFFFu) * DD + d0;
        const float* cb = comboL + ((mc >> 16) & 7u) * DD;

        const F8     r  = ldg_keep32(Rp);
        const float4 cA = __ldg((const float4*)cb);
        const float4 cB = __ldg((const float4*)(cb + 4));

        float4 oA, oB;
        oA.x = r.f[0] + cA.x;  oA.y = r.f[1] + cA.y;
        oA.z = r.f[2] + cA.z;  oA.w = r.f[3] + cA.w;
        oB.x = r.f[4] + cB.x;  oB.y = r.f[5] + cB.y;
        oB.z = r.f[6] + cB.z;  oB.w = r.f[7] + cB.w;

        if (!(mc >> 31)) {
            oA.x = oA.y = oA.z = oA.w = 0.0f;
            oB.x = oB.y = oB.z = oB.w = 0.0f;
        }

        stg_cs(out + oofs,     oA);
        stg_cs(out + oofs + 4, oB);
        oofs += OSTEP;
    }
}

extern "C" void kernel_launch(void* const* d_in, const int* in_sizes, int n_in,
                              void* d_out, int out_size)
{
    const int*   token_ids = (const int*)  d_in[0];
    const int*   actors    = (const int*)  d_in[1];
    const int*   streets   = (const int*)  d_in[2];
    const float* masks     = (const float*)d_in[3];
    const float* actor_w   = (const float*)d_in[4];
    const float* street_w  = (const float*)d_in[5];
    const float* pos_w     = (const float*)d_in[6];
    const float* mlp_w     = (const float*)d_in[7];
    const float* mlp_b     = (const float*)d_in[8];
    const float* ln_g      = (const float*)d_in[9];
    const float* ln_b      = (const float*)d_in[10];
    float*       out       = (float*)d_out;

    precompute1<<<512 + LL * 8, 256>>>(mlp_w, mlp_b, actor_w, street_w, pos_w);
    build_relu<<<65536 / 8, 256>>>(ln_g, ln_b);
    prepass<<<BB, LL>>>(token_ids, actors, streets, masks);
    action_emb_kernel<<<NBLOCKS, THREADS>>>(out);
}

// round 9
// speedup vs baseline: 1.0442x; 1.0442x over previous
#include <cuda_runtime.h>
#include <cuda_fp16.h>
#include <cstdint>

#define SS 160
#define LL 128
#define DD 256
#define KK 16
#define BB 2048

#define THREADS 256
#define B_PER_BLOCK 64
#define ROWS_PER_WARP 8
#define NBLOCKS (LL * (BB / B_PER_BLOCK))   // 4096

__device__ float    g_H[2 * 256 * DD];      // byte tables, bias folded into H0
__device__ float    g_combo[LL * 8 * DD];   // pos + actor + street per (l, a*4+s)
__device__ __half2  g_R[65536 * (DD / 2)];  // relu(LN(h)) per pattern, fp16 (32 MB)
__device__ unsigned g_meta[BB * LL];        // pat | a4s<<16 | valid<<31

// ---------- K1: byte tables + combo ----------
__global__ void precompute1(const float* __restrict__ mlp_w,
                            const float* __restrict__ mlp_b,
                            const float* __restrict__ actor_w,
                            const float* __restrict__ street_w,
                            const float* __restrict__ pos_w)
{
    const int d   = threadIdx.x;
    const int bid = blockIdx.x;
    if (bid < 512) {
        const int half = bid >> 8;
        const int q    = bid & 255;
        float acc = (half == 0) ? mlp_b[d] : 0.0f;
#pragma unroll
        for (int k = 0; k < 8; k++)
            if ((q >> k) & 1) acc += mlp_w[(half * 8 + k) * DD + d];
        g_H[bid * DD + d] = acc;
    } else {
        const int cb = bid - 512;              // l*8 + (a*4+s)
        const int c  = cb & 7;
        const int l  = cb >> 3;
        g_combo[cb * DD + d] =
            actor_w[(c >> 2) * DD + d] + street_w[(c & 3) * DD + d] + pos_w[l * DD + d];
    }
}

// ---------- K2: build R (fp16) for all patterns + metadata prepass (merged) ----------
__global__ __launch_bounds__(256, 4)
void build_relu_prepass(const float* __restrict__ ln_g,
                        const float* __restrict__ ln_b,
                        const int*   __restrict__ token_ids,
                        const int*   __restrict__ actors,
                        const int*   __restrict__ streets,
                        const float* __restrict__ masks)
{
    const int bid = blockIdx.x;
    if (bid < 8192) {
        // ---- R table: 8 warps, one pattern each ----
        const int lane = threadIdx.x & 31;
        const int p    = bid * 8 + (threadIdx.x >> 5);
        const int d0   = lane * 8;

        const float* H0 = g_H + ((p & 255)      ) * DD + d0;
        const float* H1 = g_H + ((p >> 8) + 256 ) * DD + d0;
        const float4 a0 = __ldg((const float4*)H0);
        const float4 a1 = __ldg((const float4*)(H0 + 4));
        const float4 b0 = __ldg((const float4*)H1);
        const float4 b1 = __ldg((const float4*)(H1 + 4));

        const float h0 = a0.x + b0.x, h1 = a0.y + b0.y, h2 = a0.z + b0.z, h3 = a0.w + b0.w;
        const float h4 = a1.x + b1.x, h5 = a1.y + b1.y, h6 = a1.z + b1.z, h7 = a1.w + b1.w;

        float s  = ((h0 + h1) + (h2 + h3)) + ((h4 + h5) + (h6 + h7));
        float sq = fmaf(h0, h0, fmaf(h1, h1, fmaf(h2, h2, h3 * h3)))
                 + fmaf(h4, h4, fmaf(h5, h5, fmaf(h6, h6, h7 * h7)));
#pragma unroll
        for (int o = 16; o > 0; o >>= 1) {
            s  += __shfl_xor_sync(0xffffffffu, s,  o);
            sq += __shfl_xor_sync(0xffffffffu, sq, o);
        }
        const float mu   = s * (1.0f / DD);
        const float var  = fmaf(-mu, mu, sq * (1.0f / DD));
        const float rs   = rsqrtf(var + 1e-5f);
        const float nmrs = -mu * rs;

        const float4 gA = __ldg((const float4*)(ln_g + d0));
        const float4 gB = __ldg((const float4*)(ln_g + d0 + 4));
        const float4 bA = __ldg((const float4*)(ln_b + d0));
        const float4 bB = __ldg((const float4*)(ln_b + d0 + 4));

        float r0 = fmaxf(fmaf(fmaf(h0, rs, nmrs), gA.x, bA.x), 0.0f);
        float r1 = fmaxf(fmaf(fmaf(h1, rs, nmrs), gA.y, bA.y), 0.0f);
        float r2 = fmaxf(fmaf(fmaf(h2, rs, nmrs), gA.z, bA.z), 0.0f);
        float r3 = fmaxf(fmaf(fmaf(h3, rs, nmrs), gA.w, bA.w), 0.0f);
        float r4 = fmaxf(fmaf(fmaf(h4, rs, nmrs), gB.x, bB.x), 0.0f);
        float r5 = fmaxf(fmaf(fmaf(h5, rs, nmrs), gB.y, bB.y), 0.0f);
        float r6 = fmaxf(fmaf(fmaf(h6, rs, nmrs), gB.z, bB.z), 0.0f);
        float r7 = fmaxf(fmaf(fmaf(h7, rs, nmrs), gB.w, bB.w), 0.0f);

        __half2 v0 = __float22half2_rn(make_float2(r0, r1));
        __half2 v1 = __float22half2_rn(make_float2(r2, r3));
        __half2 v2 = __float22half2_rn(make_float2(r4, r5));
        __half2 v3 = __float22half2_rn(make_float2(r6, r7));

        uint4 st;
        st.x = *(unsigned*)&v0;  st.y = *(unsigned*)&v1;
        st.z = *(unsigned*)&v2;  st.w = *(unsigned*)&v3;
        *(uint4*)(g_R + (size_t)p * (DD / 2) + lane * 4) = st;
    } else {
        // ---- metadata prepass: 2 b-rows per block ----
        const int tid = threadIdx.x;
        const int b   = (bid - 8192) * 2 + (tid >> 7);
        const int l   = tid & 127;
        const long idc = (long)b * SS + l;
        const float4* mp = (const float4*)(masks + idc * KK);
        const float4 m0 = __ldg(mp + 0);
        const float4 m1 = __ldg(mp + 1);
        const float4 m2 = __ldg(mp + 2);
        const float4 m3 = __ldg(mp + 3);

        unsigned pat = 0;
        pat |= (m0.x != 0.f) ? 1u       : 0u;
        pat |= (m0.y != 0.f) ? 1u <<  1 : 0u;
        pat |= (m0.z != 0.f) ? 1u <<  2 : 0u;
        pat |= (m0.w != 0.f) ? 1u <<  3 : 0u;
        pat |= (m1.x != 0.f) ? 1u <<  4 : 0u;
        pat |= (m1.y != 0.f) ? 1u <<  5 : 0u;
        pat |= (m1.z != 0.f) ? 1u <<  6 : 0u;
        pat |= (m1.w != 0.f) ? 1u <<  7 : 0u;
        pat |= (m2.x != 0.f) ? 1u <<  8 : 0u;
        pat |= (m2.y != 0.f) ? 1u <<  9 : 0u;
        pat |= (m2.z != 0.f) ? 1u << 10 : 0u;
        pat |= (m2.w != 0.f) ? 1u << 11 : 0u;
        pat |= (m3.x != 0.f) ? 1u << 12 : 0u;
        pat |= (m3.y != 0.f) ? 1u << 13 : 0u;
        pat |= (m3.z != 0.f) ? 1u << 14 : 0u;
        pat |= (m3.w != 0.f) ? 1u << 15 : 0u;

        const int tok = __ldg(token_ids + idc);
        const int a   = __ldg(actors    + idc);
        const int s   = __ldg(streets   + idc);

        unsigned meta = pat | ((unsigned)(a * 4 + s) << 16);
        if (tok >= 0) meta |= 1u << 31;
        g_meta[b * LL + l] = meta;
    }
}

// ---------- streaming store ----------
__device__ __forceinline__ void stg_cs(float* p, float4 v) {
    asm volatile("st.global.cs.v4.f32 [%0], {%1,%2,%3,%4};"
                 :: "l"(p), "f"(v.x), "f"(v.y), "f"(v.z), "f"(v.w) : "memory");
}

// ---------- main kernel: out = R[pat] + combo, masked ----------
__global__ __launch_bounds__(THREADS, 6)
void action_emb_kernel(float* __restrict__ out)
{
    const int tid  = threadIdx.x;
    const int lane = tid & 31;
    const int warp = tid >> 5;
    const int d0   = lane * 8;

    const int l     = blockIdx.x & (LL - 1);
    const int chunk = blockIdx.x >> 7;
    const int b0    = chunk * B_PER_BLOCK + warp * ROWS_PER_WARP;

    const float* comboL = g_combo + (l * 8) * DD + d0;

    unsigned m32 = 0;
    if (lane < ROWS_PER_WARP) m32 = g_meta[(b0 + lane) * LL + l];

    int oofs = (b0 * LL + l) * DD + d0;
    const int OSTEP = LL * DD;

#pragma unroll
    for (int it = 0; it < ROWS_PER_WARP; it++) {
        const unsigned mc = __shfl_sync(0xffffffffu, m32, it);
        const __half2* Rp = g_R + (size_t)(mc & 0xFFFFu) * (DD / 2) + lane * 4;
        const float*   cb = comboL + ((mc >> 16) & 7u) * DD;

        const uint4  rh = __ldg((const uint4*)Rp);
        const float4 cA = __ldg((const float4*)cb);
        const float4 cB = __ldg((const float4*)(cb + 4));

        const float2 f0 = __half22float2(*(const __half2*)&rh.x);
        const float2 f1 = __half22float2(*(const __half2*)&rh.y);
        const float2 f2 = __half22float2(*(const __half2*)&rh.z);
        const float2 f3 = __half22float2(*(const __half2*)&rh.w);

        float4 oA, oB;
        oA.x = f0.x + cA.x;  oA.y = f0.y + cA.y;
        oA.z = f1.x + cA.z;  oA.w = f1.y + cA.w;
        oB.x = f2.x + cB.x;  oB.y = f2.y + cB.y;
        oB.z = f3.x + cB.z;  oB.w = f3.y + cB.w;

        if (!(mc >> 31)) {
            oA.x = oA.y = oA.z = oA.w = 0.0f;
            oB.x = oB.y = oB.z = oB.w = 0.0f;
        }

        stg_cs(out + oofs,     oA);
        stg_cs(out + oofs + 4, oB);
        oofs += OSTEP;
    }
}

extern "C" void kernel_launch(void* const* d_in, const int* in_sizes, int n_in,
                              void* d_out, int out_size)
{
    const int*   token_ids = (const int*)  d_in[0];
    const int*   actors    = (const int*)  d_in[1];
    const int*   streets   = (const int*)  d_in[2];
    const float* masks     = (const float*)d_in[3];
    const float* actor_w   = (const float*)d_in[4];
    const float* street_w  = (const float*)d_in[5];
    const float* pos_w     = (const float*)d_in[6];
    const float* mlp_w     = (const float*)d_in[7];
    const float* mlp_b     = (const float*)d_in[8];
    const float* ln_g      = (const float*)d_in[9];
    const float* ln_b      = (const float*)d_in[10];
    float*       out       = (float*)d_out;

    precompute1<<<512 + LL * 8, 256>>>(mlp_w, mlp_b, actor_w, street_w, pos_w);
    build_relu_prepass<<<8192 + BB / 2, 256>>>(ln_g, ln_b,
                                               token_ids, actors, streets, masks);
    action_emb_kernel<<<NBLOCKS, THREADS>>>(out);
}

// round 10
// speedup vs baseline: 1.2682x; 1.2145x over previous
#include <cuda_runtime.h>
#include <cuda_fp16.h>
#include <cstdint>

#define SS 160
#define LL 128
#define DD 256
#define KK 16
#define BB 2048

#define THREADS 256
#define B_PER_BLOCK 64
#define ROWS_PER_WARP 8
#define NBLOCKS (LL * (BB / B_PER_BLOCK))   // 4096

__device__ __half2  g_Hh[2 * 256 * (DD / 2)];     // byte tables fp16, bias in H0 (256 KB)
__device__ __half2  g_comboh[LL * 8 * (DD / 2)];  // pos+actor+street fp16 (512 KB)
__device__ float    g_T[64 * DD];                 // nibble tables fp32 (stats math)
__device__ float    g_S[64], g_Q[64];
__device__ float    g_D[6 * 256];
__device__ float2   g_stats[65536];               // (mu, rsqrt) per pattern
__device__ unsigned g_meta[BB * LL];              // pat | a4s<<16 | valid<<31

// ---------- K1: H(fp16) + T(fp32) + combo(fp16) + metadata prepass ----------
__global__ void precompute1(const float* __restrict__ mlp_w,
                            const float* __restrict__ mlp_b,
                            const float* __restrict__ actor_w,
                            const float* __restrict__ street_w,
                            const float* __restrict__ pos_w,
                            const int*   __restrict__ token_ids,
                            const int*   __restrict__ actors,
                            const int*   __restrict__ streets,
                            const float* __restrict__ masks)
{
    const int tid = threadIdx.x;
    const int bid = blockIdx.x;
    __shared__ float buf[DD];

    if (bid < 512) {
        // byte tables, fp16
        const int half = bid >> 8;
        const int q    = bid & 255;
        const int d    = tid;
        float acc = (half == 0) ? mlp_b[d] : 0.0f;
#pragma unroll
        for (int k = 0; k < 8; k++)
            if ((q >> k) & 1) acc += mlp_w[(half * 8 + k) * DD + d];
        buf[d] = acc;
        __syncthreads();
        if (d < DD / 2)
            g_Hh[bid * (DD / 2) + d] =
                __float22half2_rn(make_float2(buf[d * 2], buf[d * 2 + 1]));
    } else if (bid < 576) {
        // nibble tables fp32 (for stats algebra)
        const int idx = bid - 512;           // 0..63
        const int i = idx >> 4, q = idx & 15;
        const int d = tid;
        float acc = (i == 0) ? mlp_b[d] : 0.0f;
#pragma unroll
        for (int k = 0; k < 4; k++)
            if ((q >> k) & 1) acc += mlp_w[(i * 4 + k) * DD + d];
        g_T[idx * DD + d] = acc;
    } else if (bid < 576 + LL * 8) {
        // combo fp16
        const int cb = bid - 576;            // l*8 + (a*4+s)
        const int c  = cb & 7;
        const int l  = cb >> 3;
        const int d  = tid;
        buf[d] = actor_w[(c >> 2) * DD + d] + street_w[(c & 3) * DD + d]
               + pos_w[l * DD + d];
        __syncthreads();
        if (d < DD / 2)
            g_comboh[cb * (DD / 2) + d] =
                __float22half2_rn(make_float2(buf[d * 2], buf[d * 2 + 1]));
    } else {
        // metadata prepass: 2 b-rows per block
        const int b = (bid - (576 + LL * 8)) * 2 + (tid >> 7);
        const int l = tid & 127;
        const long idc = (long)b * SS + l;
        const float4* mp = (const float4*)(masks + idc * KK);
        const float4 m0 = __ldg(mp + 0);
        const float4 m1 = __ldg(mp + 1);
        const float4 m2 = __ldg(mp + 2);
        const float4 m3 = __ldg(mp + 3);

        unsigned pat = 0;
        pat |= (m0.x != 0.f) ? 1u       : 0u;
        pat |= (m0.y != 0.f) ? 1u <<  1 : 0u;
        pat |= (m0.z != 0.f) ? 1u <<  2 : 0u;
        pat |= (m0.w != 0.f) ? 1u <<  3 : 0u;
        pat |= (m1.x != 0.f) ? 1u <<  4 : 0u;
        pat |= (m1.y != 0.f) ? 1u <<  5 : 0u;
        pat |= (m1.z != 0.f) ? 1u <<  6 : 0u;
        pat |= (m1.w != 0.f) ? 1u <<  7 : 0u;
        pat |= (m2.x != 0.f) ? 1u <<  8 : 0u;
        pat |= (m2.y != 0.f) ? 1u <<  9 : 0u;
        pat |= (m2.z != 0.f) ? 1u << 10 : 0u;
        pat |= (m2.w != 0.f) ? 1u << 11 : 0u;
        pat |= (m3.x != 0.f) ? 1u << 12 : 0u;
        pat |= (m3.y != 0.f) ? 1u << 13 : 0u;
        pat |= (m3.z != 0.f) ? 1u << 14 : 0u;
        pat |= (m3.w != 0.f) ? 1u << 15 : 0u;

        const int tok = __ldg(token_ids + idc);
        const int a   = __ldg(actors    + idc);
        const int s   = __ldg(streets   + idc);

        unsigned meta = pat | ((unsigned)(a * 4 + s) << 16);
        if (tok >= 0) meta |= 1u << 31;
        g_meta[b * LL + l] = meta;
    }
}

// ---------- K2: per-nibble sums/sumsqs + pairwise dot tables ----------
__global__ void precompute2()
{
    const int lane = threadIdx.x;
    const int bid  = blockIdx.x;
    const int d    = lane * 8;

    if (bid < 1536) {
        const int pair = bid >> 8;
        const int e    = bid & 255;
        const int qi   = e >> 4, qj = e & 15;
        const int pi[6] = {0, 0, 0, 1, 1, 2};
        const int pj[6] = {1, 2, 3, 2, 3, 3};
        const float* ti = g_T + (pi[pair] * 16 + qi) * DD + d;
        const float* tj = g_T + (pj[pair] * 16 + qj) * DD + d;
        const float4 a0 = *(const float4*)ti;
        const float4 a1 = *(const float4*)(ti + 4);
        const float4 b0 = *(const float4*)tj;
        const float4 b1 = *(const float4*)(tj + 4);
        float acc = a0.x*b0.x + a0.y*b0.y + a0.z*b0.z + a0.w*b0.w
                  + a1.x*b1.x + a1.y*b1.y + a1.z*b1.z + a1.w*b1.w;
#pragma unroll
        for (int o = 16; o > 0; o >>= 1)
            acc += __shfl_xor_sync(0xffffffffu, acc, o);
        if (lane == 0) g_D[pair * 256 + e] = acc;
    } else {
        const int s = bid - 1536;
        const float* t = g_T + s * DD + d;
        const float4 a0 = *(const float4*)t;
        const float4 a1 = *(const float4*)(t + 4);
        float sum = (a0.x + a0.y) + (a0.z + a0.w)
                  + (a1.x + a1.y) + (a1.z + a1.w);
        float sq  = a0.x*a0.x + a0.y*a0.y + a0.z*a0.z + a0.w*a0.w
                  + a1.x*a1.x + a1.y*a1.y + a1.z*a1.z + a1.w*a1.w;
#pragma unroll
        for (int o = 16; o > 0; o >>= 1) {
            sum += __shfl_xor_sync(0xffffffffu, sum, o);
            sq  += __shfl_xor_sync(0xffffffffu, sq,  o);
        }
        if (lane == 0) { g_S[s] = sum; g_Q[s] = sq; }
    }
}

// ---------- K3: LN stats per pattern ----------
__global__ void precompute3()
{
    const int p  = blockIdx.x * 256 + threadIdx.x;
    const int q0 = p & 15, q1 = (p >> 4) & 15, q2 = (p >> 8) & 15, q3 = p >> 12;
    const float sum = g_S[q0] + g_S[16 + q1] + g_S[32 + q2] + g_S[48 + q3];
    const float sq  = g_Q[q0] + g_Q[16 + q1] + g_Q[32 + q2] + g_Q[48 + q3]
        + 2.0f * ( g_D[0*256 + q0*16 + q1] + g_D[1*256 + q0*16 + q2]
                 + g_D[2*256 + q0*16 + q3] + g_D[3*256 + q1*16 + q2]
                 + g_D[4*256 + q1*16 + q3] + g_D[5*256 + q2*16 + q3]);
    const float mu  = sum * (1.0f / DD);
    const float var = fmaf(-mu, mu, sq * (1.0f / DD));
    float2 r; r.x = mu; r.y = rsqrtf(var + 1e-5f);
    g_stats[p] = r;
}

// ---------- streaming store ----------
__device__ __forceinline__ void stg_cs(float* p, float4 v) {
    asm volatile("st.global.cs.v4.f32 [%0], {%1,%2,%3,%4};"
                 :: "l"(p), "f"(v.x), "f"(v.y), "f"(v.z), "f"(v.w) : "memory");
}

// ---------- main kernel ----------
__global__ __launch_bounds__(THREADS, 6)
void action_emb_kernel(const float* __restrict__ ln_g,
                       const float* __restrict__ ln_b,
                       float*       __restrict__ out)
{
    const int tid  = threadIdx.x;
    const int lane = tid & 31;
    const int warp = tid >> 5;
    const int d0   = lane * 8;

    const int l     = blockIdx.x & (LL - 1);
    const int chunk = blockIdx.x >> 7;
    const int b0    = chunk * B_PER_BLOCK + warp * ROWS_PER_WARP;

    const float4 gA = *(const float4*)(ln_g + d0);
    const float4 gB = *(const float4*)(ln_g + d0 + 4);
    const float4 bA = *(const float4*)(ln_b + d0);
    const float4 bB = *(const float4*)(ln_b + d0 + 4);

    const __half2* comboL = g_comboh + (l * 8) * (DD / 2) + lane * 4;

    unsigned m32 = 0;
    if (lane < ROWS_PER_WARP) m32 = g_meta[(b0 + lane) * LL + l];

    int oofs = (b0 * LL + l) * DD + d0;
    const int OSTEP = LL * DD;

#pragma unroll
    for (int it = 0; it < ROWS_PER_WARP; it++) {
        const unsigned mc  = __shfl_sync(0xffffffffu, m32, it);
        const unsigned pat = mc & 0xFFFFu;

        const uint4 h0v = __ldg((const uint4*)(g_Hh + ((pat & 255u)      ) * (DD/2) + lane * 4));
        const uint4 h1v = __ldg((const uint4*)(g_Hh + ((pat >> 8) + 256u ) * (DD/2) + lane * 4));
        const uint4 cv  = __ldg((const uint4*)(comboL + ((mc >> 16) & 7u) * (DD/2)));
        const float2 st = __ldg(&g_stats[pat]);

        const float2 a0 = __half22float2(*(const __half2*)&h0v.x);
        const float2 a1 = __half22float2(*(const __half2*)&h0v.y);
        const float2 a2 = __half22float2(*(const __half2*)&h0v.z);
        const float2 a3 = __half22float2(*(const __half2*)&h0v.w);
        const float2 e0 = __half22float2(*(const __half2*)&h1v.x);
        const float2 e1 = __half22float2(*(const __half2*)&h1v.y);
        const float2 e2 = __half22float2(*(const __half2*)&h1v.z);
        const float2 e3 = __half22float2(*(const __half2*)&h1v.w);
        const float2 c0 = __half22float2(*(const __half2*)&cv.x);
        const float2 c1 = __half22float2(*(const __half2*)&cv.y);
        const float2 c2 = __half22float2(*(const __half2*)&cv.z);
        const float2 c3 = __half22float2(*(const __half2*)&cv.w);

        const float rs   = st.y;
        const float nmrs = -st.x * rs;

        float4 oA, oB;
        oA.x = fmaxf(fmaf(fmaf(a0.x + e0.x, rs, nmrs), gA.x, bA.x), 0.0f) + c0.x;
        oA.y = fmaxf(fmaf(fmaf(a0.y + e0.y, rs, nmrs), gA.y, bA.y), 0.0f) + c0.y;
        oA.z = fmaxf(fmaf(fmaf(a1.x + e1.x, rs, nmrs), gA.z, bA.z), 0.0f) + c1.x;
        oA.w = fmaxf(fmaf(fmaf(a1.y + e1.y, rs, nmrs), gA.w, bA.w), 0.0f) + c1.y;
        oB.x = fmaxf(fmaf(fmaf(a2.x + e2.x, rs, nmrs), gB.x, bB.x), 0.0f) + c2.x;
        oB.y = fmaxf(fmaf(fmaf(a2.y + e2.y, rs, nmrs), gB.y, bB.y), 0.0f) + c2.y;
        oB.z = fmaxf(fmaf(fmaf(a3.x + e3.x, rs, nmrs), gB.z, bB.z), 0.0f) + c3.x;
        oB.w = fmaxf(fmaf(fmaf(a3.y + e3.y, rs, nmrs), gB.w, bB.w), 0.0f) + c3.y;

        if (!(mc >> 31)) {
            oA.x = oA.y = oA.z = oA.w = 0.0f;
            oB.x = oB.y = oB.z = oB.w = 0.0f;
        }

        stg_cs(out + oofs,     oA);
        stg_cs(out + oofs + 4, oB);
        oofs += OSTEP;
    }
}

extern "C" void kernel_launch(void* const* d_in, const int* in_sizes, int n_in,
                              void* d_out, int out_size)
{
    const int*   token_ids = (const int*)  d_in[0];
    const int*   actors    = (const int*)  d_in[1];
    const int*   streets   = (const int*)  d_in[2];
    const float* masks     = (const float*)d_in[3];
    const float* actor_w   = (const float*)d_in[4];
    const float* street_w  = (const float*)d_in[5];
    const float* pos_w     = (const float*)d_in[6];
    const float* mlp_w     = (const float*)d_in[7];
    const float* mlp_b     = (const float*)d_in[8];
    const float* ln_g      = (const float*)d_in[9];
    const float* ln_b      = (const float*)d_in[10];
    float*       out       = (float*)d_out;

    precompute1<<<576 + LL * 8 + BB / 2, 256>>>(
        mlp_w, mlp_b, actor_w, street_w, pos_w,
        token_ids, actors, streets, masks);
    precompute2<<<1600, 32>>>();
    precompute3<<<256, 256>>>();
    action_emb_kernel<<<NBLOCKS, THREADS>>>(ln_g, ln_b, out);
}

// round 11
// speedup vs baseline: 1.8474x; 1.4567x over previous
#include <cuda_runtime.h>
#include <cuda_fp16.h>
#include <cstdint>

#define SS 160
#define LL 128
#define DD 256
#define KK 16
#define BB 2048

#define THREADS 256
#define B_PER_BLOCK 64
#define ROWS_PER_WARP 8
#define NBLOCKS (LL * (BB / B_PER_BLOCK))   // 4096

// three split tables: 6+5+5 bits, 64 KB total fp16 -> L1-resident
__device__ __half2  g_T0h[64 * (DD / 2)];         // bits 0-5, bias folded
__device__ __half2  g_T1h[32 * (DD / 2)];         // bits 6-10
__device__ __half2  g_T2h[32 * (DD / 2)];         // bits 11-15
__device__ __half2  g_comboh[LL * 8 * (DD / 2)];  // pos+actor+street fp16
__device__ float    g_T[64 * DD];                 // nibble tables fp32 (stats math)
__device__ float    g_S[64], g_Q[64];
__device__ float    g_D[6 * 256];
__device__ float2   g_stats[65536];               // (mu, rsqrt) per pattern
__device__ unsigned g_meta[BB * LL];              // pat | a4s<<16 | valid<<31

// ---------- K1: split tables + nibble T + combo + metadata prepass ----------
__global__ void precompute1(const float* __restrict__ mlp_w,
                            const float* __restrict__ mlp_b,
                            const float* __restrict__ actor_w,
                            const float* __restrict__ street_w,
                            const float* __restrict__ pos_w,
                            const int*   __restrict__ token_ids,
                            const int*   __restrict__ actors,
                            const int*   __restrict__ streets,
                            const float* __restrict__ masks)
{
    const int tid = threadIdx.x;
    const int bid = blockIdx.x;
    __shared__ float buf[DD];

    if (bid < 128) {
        // split tables fp16: [0,64) -> T0 (6 bits), [64,96) -> T1, [96,128) -> T2
        const int d = tid;
        float acc;
        __half2* dst;
        if (bid < 64) {
            const int q = bid;
            acc = mlp_b[d];
#pragma unroll
            for (int k = 0; k < 6; k++)
                if ((q >> k) & 1) acc += mlp_w[k * DD + d];
            dst = g_T0h + bid * (DD / 2);
        } else if (bid < 96) {
            const int q = bid - 64;
            acc = 0.0f;
#pragma unroll
            for (int k = 0; k < 5; k++)
                if ((q >> k) & 1) acc += mlp_w[(6 + k) * DD + d];
            dst = g_T1h + (bid - 64) * (DD / 2);
        } else {
            const int q = bid - 96;
            acc = 0.0f;
#pragma unroll
            for (int k = 0; k < 5; k++)
                if ((q >> k) & 1) acc += mlp_w[(11 + k) * DD + d];
            dst = g_T2h + (bid - 96) * (DD / 2);
        }
        buf[d] = acc;
        __syncthreads();
        if (d < DD / 2)
            dst[d] = __float22half2_rn(make_float2(buf[d * 2], buf[d * 2 + 1]));
    } else if (bid < 192) {
        // nibble tables fp32 (for exact stats algebra)
        const int idx = bid - 128;           // 0..63
        const int i = idx >> 4, q = idx & 15;
        const int d = tid;
        float acc = (i == 0) ? mlp_b[d] : 0.0f;
#pragma unroll
        for (int k = 0; k < 4; k++)
            if ((q >> k) & 1) acc += mlp_w[(i * 4 + k) * DD + d];
        g_T[idx * DD + d] = acc;
    } else if (bid < 192 + LL * 8) {
        // combo fp16
        const int cb = bid - 192;            // l*8 + (a*4+s)
        const int c  = cb & 7;
        const int l  = cb >> 3;
        const int d  = tid;
        buf[d] = actor_w[(c >> 2) * DD + d] + street_w[(c & 3) * DD + d]
               + pos_w[l * DD + d];
        __syncthreads();
        if (d < DD / 2)
            g_comboh[cb * (DD / 2) + d] =
                __float22half2_rn(make_float2(buf[d * 2], buf[d * 2 + 1]));
    } else {
        // metadata prepass: 2 b-rows per block
        const int b = (bid - (192 + LL * 8)) * 2 + (tid >> 7);
        const int l = tid & 127;
        const long idc = (long)b * SS + l;
        const float4* mp = (const float4*)(masks + idc * KK);
        const float4 m0 = __ldg(mp + 0);
        const float4 m1 = __ldg(mp + 1);
        const float4 m2 = __ldg(mp + 2);
        const float4 m3 = __ldg(mp + 3);

        unsigned pat = 0;
        pat |= (m0.x != 0.f) ? 1u       : 0u;
        pat |= (m0.y != 0.f) ? 1u <<  1 : 0u;
        pat |= (m0.z != 0.f) ? 1u <<  2 : 0u;
        pat |= (m0.w != 0.f) ? 1u <<  3 : 0u;
        pat |= (m1.x != 0.f) ? 1u <<  4 : 0u;
        pat |= (m1.y != 0.f) ? 1u <<  5 : 0u;
        pat |= (m1.z != 0.f) ? 1u <<  6 : 0u;
        pat |= (m1.w != 0.f) ? 1u <<  7 : 0u;
        pat |= (m2.x != 0.f) ? 1u <<  8 : 0u;
        pat |= (m2.y != 0.f) ? 1u <<  9 : 0u;
        pat |= (m2.z != 0.f) ? 1u << 10 : 0u;
        pat |= (m2.w != 0.f) ? 1u << 11 : 0u;
        pat |= (m3.x != 0.f) ? 1u << 12 : 0u;
        pat |= (m3.y != 0.f) ? 1u << 13 : 0u;
        pat |= (m3.z != 0.f) ? 1u << 14 : 0u;
        pat |= (m3.w != 0.f) ? 1u << 15 : 0u;

        const int tok = __ldg(token_ids + idc);
        const int a   = __ldg(actors    + idc);
        const int s   = __ldg(streets   + idc);

        unsigned meta = pat | ((unsigned)(a * 4 + s) << 16);
        if (tok >= 0) meta |= 1u << 31;
        g_meta[b * LL + l] = meta;
    }
}

// ---------- K2: per-nibble sums/sumsqs + pairwise dot tables ----------
__global__ void precompute2()
{
    const int lane = threadIdx.x;
    const int bid  = blockIdx.x;
    const int d    = lane * 8;

    if (bid < 1536) {
        const int pair = bid >> 8;
        const int e    = bid & 255;
        const int qi   = e >> 4, qj = e & 15;
        const int pi[6] = {0, 0, 0, 1, 1, 2};
        const int pj[6] = {1, 2, 3, 2, 3, 3};
        const float* ti = g_T + (pi[pair] * 16 + qi) * DD + d;
        const float* tj = g_T + (pj[pair] * 16 + qj) * DD + d;
        const float4 a0 = *(const float4*)ti;
        const float4 a1 = *(const float4*)(ti + 4);
        const float4 b0 = *(const float4*)tj;
        const float4 b1 = *(const float4*)(tj + 4);
        float acc = a0.x*b0.x + a0.y*b0.y + a0.z*b0.z + a0.w*b0.w
                  + a1.x*b1.x + a1.y*b1.y + a1.z*b1.z + a1.w*b1.w;
#pragma unroll
        for (int o = 16; o > 0; o >>= 1)
            acc += __shfl_xor_sync(0xffffffffu, acc, o);
        if (lane == 0) g_D[pair * 256 + e] = acc;
    } else {
        const int s = bid - 1536;
        const float* t = g_T + s * DD + d;
        const float4 a0 = *(const float4*)t;
        const float4 a1 = *(const float4*)(t + 4);
        float sum = (a0.x + a0.y) + (a0.z + a0.w)
                  + (a1.x + a1.y) + (a1.z + a1.w);
        float sq  = a0.x*a0.x + a0.y*a0.y + a0.z*a0.z + a0.w*a0.w
                  + a1.x*a1.x + a1.y*a1.y + a1.z*a1.z + a1.w*a1.w;
#pragma unroll
        for (int o = 16; o > 0; o >>= 1) {
            sum += __shfl_xor_sync(0xffffffffu, sum, o);
            sq  += __shfl_xor_sync(0xffffffffu, sq,  o);
        }
        if (lane == 0) { g_S[s] = sum; g_Q[s] = sq; }
    }
}

// ---------- K3: LN stats per pattern ----------
__global__ void precompute3()
{
    const int p  = blockIdx.x * 256 + threadIdx.x;
    const int q0 = p & 15, q1 = (p >> 4) & 15, q2 = (p >> 8) & 15, q3 = p >> 12;
    const float sum = g_S[q0] + g_S[16 + q1] + g_S[32 + q2] + g_S[48 + q3];
    const float sq  = g_Q[q0] + g_Q[16 + q1] + g_Q[32 + q2] + g_Q[48 + q3]
        + 2.0f * ( g_D[0*256 + q0*16 + q1] + g_D[1*256 + q0*16 + q2]
                 + g_D[2*256 + q0*16 + q3] + g_D[3*256 + q1*16 + q2]
                 + g_D[4*256 + q1*16 + q3] + g_D[5*256 + q2*16 + q3]);
    const float mu  = sum * (1.0f / DD);
    const float var = fmaf(-mu, mu, sq * (1.0f / DD));
    float2 r; r.x = mu; r.y = rsqrtf(var + 1e-5f);
    g_stats[p] = r;
}

// ---------- 32-byte streaming store ----------
__device__ __forceinline__ void stg_cs32(float* p, float4 a, float4 b) {
    unsigned long long r0, r1, r2, r3;
    asm("mov.b64 %0, {%1, %2};" : "=l"(r0) : "f"(a.x), "f"(a.y));
    asm("mov.b64 %0, {%1, %2};" : "=l"(r1) : "f"(a.z), "f"(a.w));
    asm("mov.b64 %0, {%1, %2};" : "=l"(r2) : "f"(b.x), "f"(b.y));
    asm("mov.b64 %0, {%1, %2};" : "=l"(r3) : "f"(b.z), "f"(b.w));
    asm volatile("st.global.cs.v4.b64 [%0], {%1,%2,%3,%4};"
                 :: "l"(p), "l"(r0), "l"(r1), "l"(r2), "l"(r3) : "memory");
}

// ---------- main kernel ----------
__global__ __launch_bounds__(THREADS, 6)
void action_emb_kernel(const float* __restrict__ ln_g,
                       const float* __restrict__ ln_b,
                       float*       __restrict__ out)
{
    const int tid  = threadIdx.x;
    const int lane = tid & 31;
    const int warp = tid >> 5;
    const int d0   = lane * 8;

    const int l     = blockIdx.x & (LL - 1);
    const int chunk = blockIdx.x >> 7;
    const int b0    = chunk * B_PER_BLOCK + warp * ROWS_PER_WARP;

    const float4 gA = *(const float4*)(ln_g + d0);
    const float4 gB = *(const float4*)(ln_g + d0 + 4);
    const float4 bA = *(const float4*)(ln_b + d0);
    const float4 bB = *(const float4*)(ln_b + d0 + 4);

    const __half2* comboL = g_comboh + (l * 8) * (DD / 2) + lane * 4;

    // lanes 0-7 own one row each: meta + stats
    unsigned m32 = 0;
    float2   st8 = make_float2(0.f, 0.f);
    if (lane < ROWS_PER_WARP) {
        m32 = g_meta[(b0 + lane) * LL + l];
        st8 = __ldg(&g_stats[m32 & 0xFFFFu]);
    }

    int oofs = (b0 * LL + l) * DD + d0;
    const int OSTEP = LL * DD;

#pragma unroll
    for (int it = 0; it < ROWS_PER_WARP; it++) {
        const unsigned mc = __shfl_sync(0xffffffffu, m32, it);
        const float    mu = __shfl_sync(0xffffffffu, st8.x, it);
        const float    rs = __shfl_sync(0xffffffffu, st8.y, it);

        const unsigned q0 =  mc        & 63u;
        const unsigned q1 = (mc >>  6) & 31u;
        const unsigned q2 = (mc >> 11) & 31u;

        const uint4 t0v = __ldg((const uint4*)(g_T0h + q0 * (DD/2) + lane * 4));
        const uint4 t1v = __ldg((const uint4*)(g_T1h + q1 * (DD/2) + lane * 4));
        const uint4 t2v = __ldg((const uint4*)(g_T2h + q2 * (DD/2) + lane * 4));
        const uint4 cv  = __ldg((const uint4*)(comboL + ((mc >> 16) & 7u) * (DD/2)));

        const float2 a0 = __half22float2(*(const __half2*)&t0v.x);
        const float2 a1 = __half22float2(*(const __half2*)&t0v.y);
        const float2 a2 = __half22float2(*(const __half2*)&t0v.z);
        const float2 a3 = __half22float2(*(const __half2*)&t0v.w);
        const float2 e0 = __half22float2(*(const __half2*)&t1v.x);
        const float2 e1 = __half22float2(*(const __half2*)&t1v.y);
        const float2 e2 = __half22float2(*(const __half2*)&t1v.z);
        const float2 e3 = __half22float2(*(const __half2*)&t1v.w);
        const float2 f0 = __half22float2(*(const __half2*)&t2v.x);
        const float2 f1 = __half22float2(*(const __half2*)&t2v.y);
        const float2 f2 = __half22float2(*(const __half2*)&t2v.z);
        const float2 f3 = __half22float2(*(const __half2*)&t2v.w);
        const float2 c0 = __half22float2(*(const __half2*)&cv.x);
        const float2 c1 = __half22float2(*(const __half2*)&cv.y);
        const float2 c2 = __half22float2(*(const __half2*)&cv.z);
        const float2 c3 = __half22float2(*(const __half2*)&cv.w);

        const float nmrs = -mu * rs;

        float4 oA, oB;
        oA.x = fmaxf(fmaf(fmaf((a0.x + e0.x) + f0.x, rs, nmrs), gA.x, bA.x), 0.0f) + c0.x;
        oA.y = fmaxf(fmaf(fmaf((a0.y + e0.y) + f0.y, rs, nmrs), gA.y, bA.y), 0.0f) + c0.y;
        oA.z = fmaxf(fmaf(fmaf((a1.x + e1.x) + f1.x, rs, nmrs), gA.z, bA.z), 0.0f) + c1.x;
        oA.w = fmaxf(fmaf(fmaf((a1.y + e1.y) + f1.y, rs, nmrs), gA.w, bA.w), 0.0f) + c1.y;
        oB.x = fmaxf(fmaf(fmaf((a2.x + e2.x) + f2.x, rs, nmrs), gB.x, bB.x), 0.0f) + c2.x;
        oB.y = fmaxf(fmaf(fmaf((a2.y + e2.y) + f2.y, rs, nmrs), gB.y, bB.y), 0.0f) + c2.y;
        oB.z = fmaxf(fmaf(fmaf((a3.x + e3.x) + f3.x, rs, nmrs), gB.z, bB.z), 0.0f) + c3.x;
        oB.w = fmaxf(fmaf(fmaf((a3.y + e3.y) + f3.y, rs, nmrs), gB.w, bB.w), 0.0f) + c3.y;

        if (!(mc >> 31)) {
            oA.x = oA.y = oA.z = oA.w = 0.0f;
            oB.x = oB.y = oB.z = oB.w = 0.0f;
        }

        stg_cs32(out + oofs, oA, oB);
        oofs += OSTEP;
    }
}

extern "C" void kernel_launch(void* const* d_in, const int* in_sizes, int n_in,
                              void* d_out, int out_size)
{
    const int*   token_ids = (const int*)  d_in[0];
    const int*   actors    = (const int*)  d_in[1];
    const int*   streets   = (const int*)  d_in[2];
    const float* masks     = (const float*)d_in[3];
    const float* actor_w   = (const float*)d_in[4];
    const float* street_w  = (const float*)d_in[5];
    const float* pos_w     = (const float*)d_in[6];
    const float* mlp_w     = (const float*)d_in[7];
    const float* mlp_b     = (const float*)d_in[8];
    const float* ln_g      = (const float*)d_in[9];
    const float* ln_b      = (const float*)d_in[10];
    float*       out       = (float*)d_out;

    precompute1<<<192 + LL * 8 + BB / 2, 256>>>(
        mlp_w, mlp_b, actor_w, street_w, pos_w,
        token_ids, actors, streets, masks);
    precompute2<<<1600, 32>>>();
    precompute3<<<256, 256>>>();
    action_emb_kernel<<<NBLOCKS, THREADS>>>(ln_g, ln_b, out);
}

// round 12
// speedup vs baseline: 1.8577x; 1.0056x over previous
#include <cuda_runtime.h>
#include <cuda_fp16.h>
#include <cstdint>

#define SS 160
#define LL 128
#define DD 256
#define KK 16
#define BB 2048

#define THREADS 256
#define B_PER_BLOCK 64
#define ROWS_PER_WARP 8
#define NBLOCKS (LL * (BB / B_PER_BLOCK))   // 4096

// K1 block ranges
#define NB_TBL   128
#define NB_SQD   200
#define NB_COMBO (LL * 8)    // 1024
#define NB_META  (BB / 2)    // 1024

// three split tables: 6+5+5 bits, 64 KB total fp16 -> L1-resident
__device__ __half2  g_T0h[64 * (DD / 2)];         // bits 0-5, bias folded
__device__ __half2  g_T1h[32 * (DD / 2)];         // bits 6-10
__device__ __half2  g_T2h[32 * (DD / 2)];         // bits 11-15
__device__ __half2  g_comboh[LL * 8 * (DD / 2)];  // pos+actor+street fp16
__device__ float    g_S[64], g_Q[64];
__device__ float    g_D[6 * 256];
__device__ float2   g_stats[65536];               // (rs, -mu*rs) per pattern
__device__ unsigned g_meta[BB * LL];              // pat | a4s<<16 | valid<<31

// recompute one fp32 nibble-table entry (i in 0..3, q in 0..15) at dims [d, d+8)
__device__ __forceinline__ void nib_entry(const float* __restrict__ mlp_w,
                                          const float* __restrict__ mlp_b,
                                          int i, int q, int d, float v[8])
{
#pragma unroll
    for (int x = 0; x < 8; x++) v[x] = (i == 0) ? mlp_b[d + x] : 0.0f;
#pragma unroll
    for (int k = 0; k < 4; k++)
        if ((q >> k) & 1) {
            const float* w = mlp_w + (i * 4 + k) * DD + d;
#pragma unroll
            for (int x = 0; x < 8; x++) v[x] += w[x];
        }
}

// ---------- K1: split tables + S/Q/D + combo + metadata prepass ----------
__global__ void precompute1(const float* __restrict__ mlp_w,
                            const float* __restrict__ mlp_b,
                            const float* __restrict__ actor_w,
                            const float* __restrict__ street_w,
                            const float* __restrict__ pos_w,
                            const int*   __restrict__ token_ids,
                            const int*   __restrict__ actors,
                            const int*   __restrict__ streets,
                            const float* __restrict__ masks)
{
    const int tid = threadIdx.x;
    const int bid = blockIdx.x;
    __shared__ float buf[DD];

    if (bid < NB_TBL) {
        // split tables fp16: [0,64) -> T0 (6 bits), [64,96) -> T1, [96,128) -> T2
        const int d = tid;
        float acc;
        __half2* dst;
        if (bid < 64) {
            const int q = bid;
            acc = mlp_b[d];
#pragma unroll
            for (int k = 0; k < 6; k++)
                if ((q >> k) & 1) acc += mlp_w[k * DD + d];
            dst = g_T0h + bid * (DD / 2);
        } else if (bid < 96) {
            const int q = bid - 64;
            acc = 0.0f;
#pragma unroll
            for (int k = 0; k < 5; k++)
                if ((q >> k) & 1) acc += mlp_w[(6 + k) * DD + d];
            dst = g_T1h + (bid - 64) * (DD / 2);
        } else {
            const int q = bid - 96;
            acc = 0.0f;
#pragma unroll
            for (int k = 0; k < 5; k++)
                if ((q >> k) & 1) acc += mlp_w[(11 + k) * DD + d];
            dst = g_T2h + (bid - 96) * (DD / 2);
        }
        buf[d] = acc;
        __syncthreads();
        if (d < DD / 2)
            dst[d] = __float22half2_rn(make_float2(buf[d * 2], buf[d * 2 + 1]));
    } else if (bid < NB_TBL + NB_SQD) {
        // S/Q/D: one work item per warp, recomputing nibble entries from mlp_w
        const int lane = tid & 31;
        const int work = (bid - NB_TBL) * 8 + (tid >> 5);   // 0..1599
        const int d    = lane * 8;

        if (work < 1536) {
            const int pair = work >> 8;
            const int e    = work & 255;
            const int qi   = e >> 4, qj = e & 15;
            const int pi[6] = {0, 0, 0, 1, 1, 2};
            const int pj[6] = {1, 2, 3, 2, 3, 3};
            float vi[8], vj[8];
            nib_entry(mlp_w, mlp_b, pi[pair], qi, d, vi);
            nib_entry(mlp_w, mlp_b, pj[pair], qj, d, vj);
            float acc = 0.f;
#pragma unroll
            for (int x = 0; x < 8; x++) acc = fmaf(vi[x], vj[x], acc);
#pragma unroll
            for (int o = 16; o > 0; o >>= 1)
                acc += __shfl_xor_sync(0xffffffffu, acc, o);
            if (lane == 0) g_D[pair * 256 + e] = acc;
        } else {
            const int s = work - 1536;          // 0..63
            float v[8];
            nib_entry(mlp_w, mlp_b, s >> 4, s & 15, d, v);
            float sum = 0.f, sq = 0.f;
#pragma unroll
            for (int x = 0; x < 8; x++) { sum += v[x]; sq = fmaf(v[x], v[x], sq); }
#pragma unroll
            for (int o = 16; o > 0; o >>= 1) {
                sum += __shfl_xor_sync(0xffffffffu, sum, o);
                sq  += __shfl_xor_sync(0xffffffffu, sq,  o);
            }
            if (lane == 0) { g_S[s] = sum; g_Q[s] = sq; }
        }
    } else if (bid < NB_TBL + NB_SQD + NB_COMBO) {
        // combo fp16
        const int cb = bid - (NB_TBL + NB_SQD);   // l*8 + (a*4+s)
        const int c  = cb & 7;
        const int l  = cb >> 3;
        const int d  = tid;
        buf[d] = actor_w[(c >> 2) * DD + d] + street_w[(c & 3) * DD + d]
               + pos_w[l * DD + d];
        __syncthreads();
        if (d < DD / 2)
            g_comboh[cb * (DD / 2) + d] =
                __float22half2_rn(make_float2(buf[d * 2], buf[d * 2 + 1]));
    } else {
        // metadata prepass: 2 b-rows per block
        const int b = (bid - (NB_TBL + NB_SQD + NB_COMBO)) * 2 + (tid >> 7);
        const int l = tid & 127;
        const long idc = (long)b * SS + l;
        const float4* mp = (const float4*)(masks + idc * KK);
        const float4 m0 = __ldg(mp + 0);
        const float4 m1 = __ldg(mp + 1);
        const float4 m2 = __ldg(mp + 2);
        const float4 m3 = __ldg(mp + 3);

        unsigned pat = 0;
        pat |= (m0.x != 0.f) ? 1u       : 0u;
        pat |= (m0.y != 0.f) ? 1u <<  1 : 0u;
        pat |= (m0.z != 0.f) ? 1u <<  2 : 0u;
        pat |= (m0.w != 0.f) ? 1u <<  3 : 0u;
        pat |= (m1.x != 0.f) ? 1u <<  4 : 0u;
        pat |= (m1.y != 0.f) ? 1u <<  5 : 0u;
        pat |= (m1.z != 0.f) ? 1u <<  6 : 0u;
        pat |= (m1.w != 0.f) ? 1u <<  7 : 0u;
        pat |= (m2.x != 0.f) ? 1u <<  8 : 0u;
        pat |= (m2.y != 0.f) ? 1u <<  9 : 0u;
        pat |= (m2.z != 0.f) ? 1u << 10 : 0u;
        pat |= (m2.w != 0.f) ? 1u << 11 : 0u;
        pat |= (m3.x != 0.f) ? 1u << 12 : 0u;
        pat |= (m3.y != 0.f) ? 1u << 13 : 0u;
        pat |= (m3.z != 0.f) ? 1u << 14 : 0u;
        pat |= (m3.w != 0.f) ? 1u << 15 : 0u;

        const int tok = __ldg(token_ids + idc);
        const int a   = __ldg(actors    + idc);
        const int s   = __ldg(streets   + idc);

        unsigned meta = pat | ((unsigned)(a * 4 + s) << 16);
        if (tok >= 0) meta |= 1u << 31;
        g_meta[b * LL + l] = meta;
    }
}

// ---------- K2: LN stats per pattern -> (rs, -mu*rs) ----------
__global__ void precompute3()
{
    const int p  = blockIdx.x * 256 + threadIdx.x;
    const int q0 = p & 15, q1 = (p >> 4) & 15, q2 = (p >> 8) & 15, q3 = p >> 12;
    const float sum = g_S[q0] + g_S[16 + q1] + g_S[32 + q2] + g_S[48 + q3];
    const float sq  = g_Q[q0] + g_Q[16 + q1] + g_Q[32 + q2] + g_Q[48 + q3]
        + 2.0f * ( g_D[0*256 + q0*16 + q1] + g_D[1*256 + q0*16 + q2]
                 + g_D[2*256 + q0*16 + q3] + g_D[3*256 + q1*16 + q2]
                 + g_D[4*256 + q1*16 + q3] + g_D[5*256 + q2*16 + q3]);
    const float mu  = sum * (1.0f / DD);
    const float var = fmaf(-mu, mu, sq * (1.0f / DD));
    const float rs  = rsqrtf(var + 1e-5f);
    float2 r; r.x = rs; r.y = -mu * rs;
    g_stats[p] = r;
}

// ---------- 32-byte streaming store ----------
__device__ __forceinline__ void stg_cs32(float* p, float4 a, float4 b) {
    unsigned long long r0, r1, r2, r3;
    asm("mov.b64 %0, {%1, %2};" : "=l"(r0) : "f"(a.x), "f"(a.y));
    asm("mov.b64 %0, {%1, %2};" : "=l"(r1) : "f"(a.z), "f"(a.w));
    asm("mov.b64 %0, {%1, %2};" : "=l"(r2) : "f"(b.x), "f"(b.y));
    asm("mov.b64 %0, {%1, %2};" : "=l"(r3) : "f"(b.z), "f"(b.w));
    asm volatile("st.global.cs.v4.b64 [%0], {%1,%2,%3,%4};"
                 :: "l"(p), "l"(r0), "l"(r1), "l"(r2), "l"(r3) : "memory");
}

// ---------- main kernel ----------
__global__ __launch_bounds__(THREADS, 6)
void action_emb_kernel(const float* __restrict__ ln_g,
                       const float* __restrict__ ln_b,
                       float*       __restrict__ out)
{
    const int tid  = threadIdx.x;
    const int lane = tid & 31;
    const int warp = tid >> 5;
    const int d0   = lane * 8;

    const int l     = blockIdx.x & (LL - 1);
    const int chunk = blockIdx.x >> 7;
    const int b0    = chunk * B_PER_BLOCK + warp * ROWS_PER_WARP;

    const float4 gA = *(const float4*)(ln_g + d0);
    const float4 gB = *(const float4*)(ln_g + d0 + 4);
    const float4 bA = *(const float4*)(ln_b + d0);
    const float4 bB = *(const float4*)(ln_b + d0 + 4);

    const __half2* comboL = g_comboh + (l * 8) * (DD / 2) + lane * 4;

    // lanes 0-7 own one row each: meta + stats
    unsigned m32 = 0;
    float2   st8 = make_float2(0.f, 0.f);
    if (lane < ROWS_PER_WARP) {
        m32 = g_meta[(b0 + lane) * LL + l];
        st8 = __ldg(&g_stats[m32 & 0xFFFFu]);
    }

    int oofs = (b0 * LL + l) * DD + d0;
    const int OSTEP = LL * DD;

#pragma unroll
    for (int it = 0; it < ROWS_PER_WARP; it++) {
        const unsigned mc   = __shfl_sync(0xffffffffu, m32, it);
        const float    rs   = __shfl_sync(0xffffffffu, st8.x, it);
        const float    nmrs = __shfl_sync(0xffffffffu, st8.y, it);

        const unsigned q0 =  mc        & 63u;
        const unsigned q1 = (mc >>  6) & 31u;
        const unsigned q2 = (mc >> 11) & 31u;

        const uint4 t0v = __ldg((const uint4*)(g_T0h + q0 * (DD/2) + lane * 4));
        const uint4 t1v = __ldg((const uint4*)(g_T1h + q1 * (DD/2) + lane * 4));
        const uint4 t2v = __ldg((const uint4*)(g_T2h + q2 * (DD/2) + lane * 4));
        const uint4 cv  = __ldg((const uint4*)(comboL + ((mc >> 16) & 7u) * (DD/2)));

        // packed fp16 sum of the three table entries
        const __half2 s0 = __hadd2(__hadd2(*(const __half2*)&t0v.x,
                                           *(const __half2*)&t1v.x),
                                   *(const __half2*)&t2v.x);
        const __half2 s1 = __hadd2(__hadd2(*(const __half2*)&t0v.y,
                                           *(const __half2*)&t1v.y),
                                   *(const __half2*)&t2v.y);
        const __half2 s2 = __hadd2(__hadd2(*(const __half2*)&t0v.z,
                                           *(const __half2*)&t1v.z),
                                   *(const __half2*)&t2v.z);
        const __half2 s3 = __hadd2(__hadd2(*(const __half2*)&t0v.w,
                                           *(const __half2*)&t1v.w),
                                   *(const __half2*)&t2v.w);

        const float2 h0 = __half22float2(s0);
        const float2 h1 = __half22float2(s1);
        const float2 h2 = __half22float2(s2);
        const float2 h3 = __half22float2(s3);

        const float2 c0 = __half22float2(*(const __half2*)&cv.x);
        const float2 c1 = __half22float2(*(const __half2*)&cv.y);
        const float2 c2 = __half22float2(*(const __half2*)&cv.z);
        const float2 c3 = __half22float2(*(const __half2*)&cv.w);

        float4 oA, oB;
        oA.x = fmaxf(fmaf(fmaf(h0.x, rs, nmrs), gA.x, bA.x), 0.0f) + c0.x;
        oA.y = fmaxf(fmaf(fmaf(h0.y, rs, nmrs), gA.y, bA.y), 0.0f) + c0.y;
        oA.z = fmaxf(fmaf(fmaf(h1.x, rs, nmrs), gA.z, bA.z), 0.0f) + c1.x;
        oA.w = fmaxf(fmaf(fmaf(h1.y, rs, nmrs), gA.w, bA.w), 0.0f) + c1.y;
        oB.x = fmaxf(fmaf(fmaf(h2.x, rs, nmrs), gB.x, bB.x), 0.0f) + c2.x;
        oB.y = fmaxf(fmaf(fmaf(h2.y, rs, nmrs), gB.y, bB.y), 0.0f) + c2.y;
        oB.z = fmaxf(fmaf(fmaf(h3.x, rs, nmrs), gB.z, bB.z), 0.0f) + c3.x;
        oB.w = fmaxf(fmaf(fmaf(h3.y, rs, nmrs), gB.w, bB.w), 0.0f) + c3.y;

        if (!(mc >> 31)) {
            oA.x = oA.y = oA.z = oA.w = 0.0f;
            oB.x = oB.y = oB.z = oB.w = 0.0f;
        }

        stg_cs32(out + oofs, oA, oB);
        oofs += OSTEP;
    }
}

extern "C" void kernel_launch(void* const* d_in, const int* in_sizes, int n_in,
                              void* d_out, int out_size)
{
    const int*   token_ids = (const int*)  d_in[0];
    const int*   actors    = (const int*)  d_in[1];
    const int*   streets   = (const int*)  d_in[2];
    const float* masks     = (const float*)d_in[3];
    const float* actor_w   = (const float*)d_in[4];
    const float* street_w  = (const float*)d_in[5];
    const float* pos_w     = (const float*)d_in[6];
    const float* mlp_w     = (const float*)d_in[7];
    const float* mlp_b     = (const float*)d_in[8];
    const float* ln_g      = (const float*)d_in[9];
    const float* ln_b      = (const float*)d_in[10];
    float*       out       = (float*)d_out;

    precompute1<<<NB_TBL + NB_SQD + NB_COMBO + NB_META, 256>>>(
        mlp_w, mlp_b, actor_w, street_w, pos_w,
        token_ids, actors, streets, masks);
    precompute3<<<256, 256>>>();
    action_emb_kernel<<<NBLOCKS, THREADS>>>(ln_g, ln_b, out);
}